// round 12
// baseline (speedup 1.0000x reference)
#include <cuda_runtime.h>
#include <stdint.h>

// MultiEchoNeighborBlock: per-pixel 7x7 KNN (k=9) over point distances,
// gather range values in exact rank order, 20->32 linear + leaky relu.
//
// R12 vs R11 (141.3us, alu=67.7, fma=30.8, occ=34.5, issue=75.0):
//  (a) BOTH echoes use the fma-flavor insert (insF): per stage 3 alu
//      (FSET + 2 FMNMX) + 3 fma (FADD + 2 FFMA) vs insA's 5 alu. Calibrated
//      from R5->R9: -11pts alu / +12.5pts fma per converted echo.
//  (b) __launch_bounds__(TPB, 4): 8 warps/SMSP. R7 proved extra occupancy is
//      useless when alu is saturated (79.6%); after (a) alu has headroom, so
//      the issue boost can convert to throughput.
// Ordering semantics unchanged (exact stable top_k, R5 proof): masks compare
// the ORIGINAL incoming key; FMNMX on non-NaN keys is value-exact; FFMA
// payload blends (m in {0,1}) are value-moves, <=1ulp, payloads only feed the
// linear layer. Triangle phase (candidate i -> min(i+1,9) stages) kept.

#define HH 64
#define WW 2048
#define HWP (HH * WW)
#define NCH 8
#define BX 128        // pixels along W per block
#define BY 2          // rows per block
#define TPB (BX * BY)
#define TW (BX + 6)   // tile width  (halo 3 each side)
#define TH (BY + 6)   // tile height

// fma-flavor stable insert, M chain stages.
// Keys: running-carry min/max identity (2 FMNMX):
//   ak_new[j] = min(c, ak[j]); c' = max(c, ak[j]).
// Payload: m = (kin < ak_old[j]) ? 1.0 : 0.0 (FSET, exact {0,1});
//   diff = cv - av[j]; av[j] += m*diff; cv -= m*diff (FADD + 2 FFMA).
// m uses the ORIGINAL kin -> ties: incoming (later index) sinks below equal
// residents, residents never re-compared -> exact top_k stable order.
template <int M>
__device__ __forceinline__ void insF(float kin, float vin,
                                     float (&ak)[9], float (&av)[9]) {
    float ck = kin, cv = vin;
#pragma unroll
    for (int j = 0; j < M; ++j) {
        float aj = ak[j];
        float m;
        asm("set.lt.f32.f32 %0, %1, %2;" : "=f"(m) : "f"(kin), "f"(aj));
        float mn = fminf(ck, aj);
        float mx = fmaxf(ck, aj);
        float diff = __fadd_rn(cv, -av[j]);
        av[j] = __fmaf_rn(m, diff, av[j]);
        cv    = __fmaf_rn(-m, diff, cv);
        ak[j] = mn;
        ck = mx;
    }
}

struct Q6 { float q0x, q0y, q0z, q1x, q1y, q1z; };

// One candidate into both echoes' arrays, M chain stages each.
template <int M>
__device__ __forceinline__ void do_cand(const float4 p, const Q6& q,
                                        float (&k0)[9], float (&v0)[9],
                                        float (&k1)[9], float (&v1)[9]) {
    // Distances: no FMA contraction (match XLA mul/add rounding), IEEE sqrt
    // (match jnp.sqrt) so the tie pattern is bit-identical to reference.
    float d0x = __fadd_rn(q.q0x, -p.x);
    float d0y = __fadd_rn(q.q0y, -p.y);
    float d0z = __fadd_rn(q.q0z, -p.z);
    float s0 = __fadd_rn(__fadd_rn(__fmul_rn(d0x, d0x), __fmul_rn(d0y, d0y)),
                         __fmul_rn(d0z, d0z));
    insF<M>(__fsqrt_rn(s0), p.w, k0, v0);

    float d1x = __fadd_rn(q.q1x, -p.x);
    float d1y = __fadd_rn(q.q1y, -p.y);
    float d1z = __fadd_rn(q.q1z, -p.z);
    float s1 = __fadd_rn(__fadd_rn(__fmul_rn(d1x, d1x), __fmul_rn(d1y, d1y)),
                         __fmul_rn(d1z, d1z));
    insF<M>(__fsqrt_rn(s1), p.w, k1, v1);
}

__global__ __launch_bounds__(TPB, 4)
void knn_block_kernel(const float* __restrict__ x,
                      const float* __restrict__ rw,
                      float* __restrict__ out) {
    __shared__ float4 tile[TH][TW];   // (px, py, pz, range_ch0)
    __shared__ float wt[20][32];      // transposed weights: wt[c][k]

    const int tid = threadIdx.x;
    const int b = blockIdx.z;
    const int h0 = blockIdx.y * BY;
    const int w0 = blockIdx.x * BX;
    const float* X = x + (size_t)b * NCH * HWP;

    for (int i = tid; i < 640; i += TPB) {
        wt[i % 20][i / 20] = rw[i];
    }
    for (int i = tid; i < TH * TW; i += TPB) {
        int r = i / TW, c = i % TW;
        int gh = h0 - 3 + r, gw = w0 - 3 + c;
        float4 v = make_float4(0.f, 0.f, 0.f, 0.f);
        if (gh >= 0 && gh < HH && gw >= 0 && gw < WW) {
            int o = gh * WW + gw;
            v.x = X[2 * HWP + o];
            v.y = X[3 * HWP + o];
            v.z = X[4 * HWP + o];
            v.w = X[0 * HWP + o];
        }
        tile[r][c] = v;
    }
    __syncthreads();

    const int tx = tid % BX;
    const int ty = tid / BX;
    const int h = h0 + ty;
    const int w = w0 + tx;
    const int pix = h * WW + w;

    const float4 c4 = tile[ty + 3][tx + 3];
    Q6 q;
    q.q0x = c4.x; q.q0y = c4.y; q.q0z = c4.z;
    q.q1x = X[5 * HWP + pix];
    q.q1y = X[6 * HWP + pix];
    q.q1z = X[7 * HWP + pix];
    const float r1c = X[1 * HWP + pix];

    const float INF = __int_as_float(0x7f800000);
    float ak0[9], av0[9], ak1[9], av1[9];
#pragma unroll
    for (int j = 0; j < 9; ++j) {
        ak0[j] = INF; av0[j] = 0.f;
        ak1[j] = INF; av1[j] = 0.f;
    }

    // Triangle phase: candidate i needs only i+1 chain stages.
    {
        const float4* r0 = &tile[ty + 0][tx];
        do_cand<1>(r0[0], q, ak0, av0, ak1, av1);
        do_cand<2>(r0[1], q, ak0, av0, ak1, av1);
        do_cand<3>(r0[2], q, ak0, av0, ak1, av1);
        do_cand<4>(r0[3], q, ak0, av0, ak1, av1);
        do_cand<5>(r0[4], q, ak0, av0, ak1, av1);
        do_cand<6>(r0[5], q, ak0, av0, ak1, av1);
        do_cand<7>(r0[6], q, ak0, av0, ak1, av1);
        const float4* r1 = &tile[ty + 1][tx];
        do_cand<8>(r1[0], q, ak0, av0, ak1, av1);
        do_cand<9>(r1[1], q, ak0, av0, ak1, av1);
        do_cand<9>(r1[2], q, ak0, av0, ak1, av1);
        do_cand<9>(r1[3], q, ak0, av0, ak1, av1);
        do_cand<9>(r1[4], q, ak0, av0, ak1, av1);
        do_cand<9>(r1[5], q, ak0, av0, ak1, av1);
        do_cand<9>(r1[6], q, ak0, av0, ak1, av1);
    }
    // Steady phase: rows 2..6.
#pragma unroll 1
    for (int dy = 2; dy < 7; ++dy) {
        const float4* row = &tile[ty + dy][tx];
#pragma unroll
        for (int dx = 0; dx < 7; ++dx)
            do_cand<9>(row[dx], q, ak0, av0, ak1, av1);
    }

    // Features: payloads sorted in rank order.
    float feats[20];
#pragma unroll
    for (int s = 0; s < 9; ++s) {
        feats[s]      = av0[s];
        feats[10 + s] = av1[s];
    }
    feats[9]  = c4.w;  // center range ch0
    feats[19] = r1c;   // center range ch1

    // 20 -> 32 linear
    float acc[32];
#pragma unroll
    for (int k = 0; k < 32; ++k) acc[k] = 0.f;
#pragma unroll
    for (int c = 0; c < 20; ++c) {
        float f = feats[c];
        const float4* wp = (const float4*)&wt[c][0];
#pragma unroll
        for (int k4 = 0; k4 < 8; ++k4) {
            float4 wv = wp[k4];
            acc[k4 * 4 + 0] += f * wv.x;
            acc[k4 * 4 + 1] += f * wv.y;
            acc[k4 * 4 + 2] += f * wv.z;
            acc[k4 * 4 + 3] += f * wv.w;
        }
    }

    float* O = out + (size_t)b * 32 * HWP + pix;
#pragma unroll
    for (int k = 0; k < 32; ++k) {
        float v = acc[k];
        v = fmaxf(v, 0.01f * v);   // leaky_relu(0.01)
        O[(size_t)k * HWP] = v;
    }
}

extern "C" void kernel_launch(void* const* d_in, const int* in_sizes, int n_in,
                              void* d_out, int out_size) {
    const float* x  = (const float*)d_in[0];
    const float* rw = (const float*)d_in[1];
    if (n_in >= 2 && in_sizes[0] == 640) {
        const float* t = x; x = rw; rw = t;
    }
    dim3 grid(WW / BX, HH / BY, 4);
    knn_block_kernel<<<grid, TPB>>>(x, rw, (float*)d_out);
}

// round 13
// speedup vs baseline: 1.0202x; 1.0202x over previous
#include <cuda_runtime.h>
#include <stdint.h>

// MultiEchoNeighborBlock: per-pixel 7x7 KNN (k=9) over point distances,
// gather range values in exact rank order, 20->32 linear + leaky relu.
//
// R13 vs R12 (142.4us, issue=81%, alu=55.6, fma=42.4 -> TOTAL-issue bound):
// cut instructions, keep pipes balanced (LP optimum: insF fraction ~2/3).
//  1. Linear layer via fma.rn.f32x2 (FFMA2): 640 FFMA -> 320 FFMA2 + 20
//     packs; weight pairs free from LDS.128 (ulonglong2 view of float4).
//  2. Distances: (p-q) packed as add.rn.f32x2 with per-pixel negated-query
//     pack + mul.rn.f32x2 -> squares bit-identical to (q-p)^2; reference
//     sum order (dx^2+dy^2)+dz^2 kept; IEEE sqrt kept -> tie pattern exact.
//  3. Echo1 alternates insA (even dx) / insF (odd dx): overall insF ~0.7.
// Stable-insert semantics unchanged (R5 proof): masks/preds compare the
// ORIGINAL incoming key; ties sink the later-index incoming; exact top_k.

#define HH 64
#define WW 2048
#define HWP (HH * WW)
#define NCH 8
#define BX 128
#define BY 2
#define TPB (BX * BY)
#define TW (BX + 6)
#define TH (BY + 6)

#define PACK2(out, lo, hi) \
    asm("mov.b64 %0, {%1, %2};" : "=l"(out) : "r"(__float_as_uint(lo)), "r"(__float_as_uint(hi)))
#define UNPACK2(lo, hi, in) \
    do { unsigned _ulo, _uhi; \
         asm("mov.b64 {%0, %1}, %2;" : "=r"(_ulo), "=r"(_uhi) : "l"(in)); \
         lo = __uint_as_float(_ulo); hi = __uint_as_float(_uhi); } while (0)
#define ADD2(out, a, b) asm("add.rn.f32x2 %0, %1, %2;" : "=l"(out) : "l"(a), "l"(b))
#define MUL2(out, a, b) asm("mul.rn.f32x2 %0, %1, %2;" : "=l"(out) : "l"(a), "l"(b))
#define FMA2(out, a, b, c) \
    asm("fma.rn.f32x2 %0, %1, %2, %3;" : "=l"(out) : "l"(a), "l"(b), "l"(c))

// alu-flavor stable insert (M stages): 1 FSETP + 4 SEL. Independent per-slot
// predicates (array sorted => kin<ak[j] monotone in j == sticky form).
template <int M>
__device__ __forceinline__ void insA(float kin, float vin,
                                     float (&ak)[9], float (&av)[9]) {
    float ck = kin, cv = vin;
#pragma unroll
    for (int j = 0; j < M; ++j) {
        bool pj = kin < ak[j];
        float tk = ak[j], tv = av[j];
        ak[j] = pj ? ck : tk;
        av[j] = pj ? cv : tv;
        ck = pj ? tk : ck;
        cv = pj ? tv : cv;
    }
}

// fma-flavor stable insert (M stages): FSET + 2 FMNMX + FADD + 2 FFMA.
// FMNMX keys exact; FFMA payload blends (mask in {0,1}) are value-moves,
// <=1ulp, payloads feed only the linear layer.
template <int M>
__device__ __forceinline__ void insF(float kin, float vin,
                                     float (&ak)[9], float (&av)[9]) {
    float ck = kin, cv = vin;
#pragma unroll
    for (int j = 0; j < M; ++j) {
        float aj = ak[j];
        float m;
        asm("set.lt.f32.f32 %0, %1, %2;" : "=f"(m) : "f"(kin), "f"(aj));
        float mn = fminf(ck, aj);
        float mx = fmaxf(ck, aj);
        float diff = __fadd_rn(cv, -av[j]);
        av[j] = __fmaf_rn(m, diff, av[j]);
        cv    = __fmaf_rn(-m, diff, cv);
        ak[j] = mn;
        ck = mx;
    }
}

struct QP {
    uint64_t nq0xy, nq1xy;   // packed (-qx, -qy) per echo
    float nq0z, nq1z;
};

// One candidate into both echoes. AFLAV=1 -> echo1 uses insA, else insF.
template <int M, int AFLAV>
__device__ __forceinline__ void do_cand(const float4 p, const QP& q,
                                        float (&k0)[9], float (&v0)[9],
                                        float (&k1)[9], float (&v1)[9]) {
    uint64_t pxy;
    PACK2(pxy, p.x, p.y);

    // Echo 0: d = p - q (squares bit-identical to q - p), ref sum order.
    uint64_t d0, s0xy;
    ADD2(d0, pxy, q.nq0xy);
    MUL2(s0xy, d0, d0);
    float d0z = __fadd_rn(p.z, q.nq0z);
    float s0x, s0y; UNPACK2(s0x, s0y, s0xy);
    float t0 = __fadd_rn(s0x, s0y);
    float s0 = __fadd_rn(t0, __fmul_rn(d0z, d0z));
    insF<M>(__fsqrt_rn(s0), p.w, k0, v0);

    // Echo 1
    uint64_t d1, s1xy;
    ADD2(d1, pxy, q.nq1xy);
    MUL2(s1xy, d1, d1);
    float d1z = __fadd_rn(p.z, q.nq1z);
    float s1x, s1y; UNPACK2(s1x, s1y, s1xy);
    float t1 = __fadd_rn(s1x, s1y);
    float s1 = __fadd_rn(t1, __fmul_rn(d1z, d1z));
    float dist1 = __fsqrt_rn(s1);
    if (AFLAV) insA<M>(dist1, p.w, k1, v1);
    else       insF<M>(dist1, p.w, k1, v1);
}

__global__ __launch_bounds__(TPB, 4)
void knn_block_kernel(const float* __restrict__ x,
                      const float* __restrict__ rw,
                      float* __restrict__ out) {
    __shared__ float4 tile[TH][TW];
    __shared__ float wt[20][32];

    const int tid = threadIdx.x;
    const int b = blockIdx.z;
    const int h0 = blockIdx.y * BY;
    const int w0 = blockIdx.x * BX;
    const float* X = x + (size_t)b * NCH * HWP;

    for (int i = tid; i < 640; i += TPB) {
        wt[i % 20][i / 20] = rw[i];
    }
    for (int i = tid; i < TH * TW; i += TPB) {
        int r = i / TW, c = i % TW;
        int gh = h0 - 3 + r, gw = w0 - 3 + c;
        float4 v = make_float4(0.f, 0.f, 0.f, 0.f);
        if (gh >= 0 && gh < HH && gw >= 0 && gw < WW) {
            int o = gh * WW + gw;
            v.x = X[2 * HWP + o];
            v.y = X[3 * HWP + o];
            v.z = X[4 * HWP + o];
            v.w = X[0 * HWP + o];
        }
        tile[r][c] = v;
    }
    __syncthreads();

    const int tx = tid % BX;
    const int ty = tid / BX;
    const int h = h0 + ty;
    const int w = w0 + tx;
    const int pix = h * WW + w;

    const float4 c4 = tile[ty + 3][tx + 3];
    QP q;
    PACK2(q.nq0xy, -c4.x, -c4.y);
    q.nq0z = -c4.z;
    float q1x = X[5 * HWP + pix];
    float q1y = X[6 * HWP + pix];
    float q1z = X[7 * HWP + pix];
    PACK2(q.nq1xy, -q1x, -q1y);
    q.nq1z = -q1z;
    const float r1c = X[1 * HWP + pix];

    const float INF = __int_as_float(0x7f800000);
    float ak0[9], av0[9], ak1[9], av1[9];
#pragma unroll
    for (int j = 0; j < 9; ++j) {
        ak0[j] = INF; av0[j] = 0.f;
        ak1[j] = INF; av1[j] = 0.f;
    }

    // Triangle phase: candidate i needs only min(i+1,9) chain stages.
    {
        const float4* r0 = &tile[ty + 0][tx];
        do_cand<1, 1>(r0[0], q, ak0, av0, ak1, av1);
        do_cand<2, 0>(r0[1], q, ak0, av0, ak1, av1);
        do_cand<3, 1>(r0[2], q, ak0, av0, ak1, av1);
        do_cand<4, 0>(r0[3], q, ak0, av0, ak1, av1);
        do_cand<5, 1>(r0[4], q, ak0, av0, ak1, av1);
        do_cand<6, 0>(r0[5], q, ak0, av0, ak1, av1);
        do_cand<7, 1>(r0[6], q, ak0, av0, ak1, av1);
        const float4* r1 = &tile[ty + 1][tx];
        do_cand<8, 0>(r1[0], q, ak0, av0, ak1, av1);
        do_cand<9, 1>(r1[1], q, ak0, av0, ak1, av1);
        do_cand<9, 0>(r1[2], q, ak0, av0, ak1, av1);
        do_cand<9, 1>(r1[3], q, ak0, av0, ak1, av1);
        do_cand<9, 0>(r1[4], q, ak0, av0, ak1, av1);
        do_cand<9, 1>(r1[5], q, ak0, av0, ak1, av1);
        do_cand<9, 0>(r1[6], q, ak0, av0, ak1, av1);
    }
    // Steady phase: rows 2..6; echo1 flavor alternates by dx parity.
#pragma unroll 1
    for (int dy = 2; dy < 7; ++dy) {
        const float4* row = &tile[ty + dy][tx];
        do_cand<9, 1>(row[0], q, ak0, av0, ak1, av1);
        do_cand<9, 0>(row[1], q, ak0, av0, ak1, av1);
        do_cand<9, 1>(row[2], q, ak0, av0, ak1, av1);
        do_cand<9, 0>(row[3], q, ak0, av0, ak1, av1);
        do_cand<9, 1>(row[4], q, ak0, av0, ak1, av1);
        do_cand<9, 0>(row[5], q, ak0, av0, ak1, av1);
        do_cand<9, 1>(row[6], q, ak0, av0, ak1, av1);
    }

    float feats[20];
#pragma unroll
    for (int s = 0; s < 9; ++s) {
        feats[s]      = av0[s];
        feats[10 + s] = av1[s];
    }
    feats[9]  = c4.w;
    feats[19] = r1c;

    // 20 -> 32 linear via packed f32x2 FFMA (two independent IEEE f32 FMAs).
    uint64_t acc2[16];
#pragma unroll
    for (int k = 0; k < 16; ++k) acc2[k] = 0ull;
#pragma unroll
    for (int c = 0; c < 20; ++c) {
        uint64_t f2;
        PACK2(f2, feats[c], feats[c]);
        const ulonglong2* wp = (const ulonglong2*)&wt[c][0];
#pragma unroll
        for (int k4 = 0; k4 < 8; ++k4) {
            ulonglong2 wv = wp[k4];          // LDS.128: two packed pairs
            FMA2(acc2[k4 * 2 + 0], f2, wv.x, acc2[k4 * 2 + 0]);
            FMA2(acc2[k4 * 2 + 1], f2, wv.y, acc2[k4 * 2 + 1]);
        }
    }

    float* O = out + (size_t)b * 32 * HWP + pix;
#pragma unroll
    for (int k2 = 0; k2 < 16; ++k2) {
        float v0, v1;
        UNPACK2(v0, v1, acc2[k2]);
        v0 = fmaxf(v0, 0.01f * v0);   // leaky_relu(0.01)
        v1 = fmaxf(v1, 0.01f * v1);
        O[(size_t)(2 * k2 + 0) * HWP] = v0;
        O[(size_t)(2 * k2 + 1) * HWP] = v1;
    }
}

extern "C" void kernel_launch(void* const* d_in, const int* in_sizes, int n_in,
                              void* d_out, int out_size) {
    const float* x  = (const float*)d_in[0];
    const float* rw = (const float*)d_in[1];
    if (n_in >= 2 && in_sizes[0] == 640) {
        const float* t = x; x = rw; rw = t;
    }
    dim3 grid(WW / BX, HH / BY, 4);
    knn_block_kernel<<<grid, TPB>>>(x, rw, (float*)d_out);
}